// round 1
// baseline (speedup 1.0000x reference)
#include <cuda_runtime.h>
#include <math.h>
#include <stdint.h>

// Problem constants (fixed by the dataset)
#define NN 100000
#define EE 400000
#define BB 512

// ---------------- scratch (no allocations allowed) ----------------
__device__ float g_degf[NN];
__device__ float g_dinv[NN];
__device__ float g_bufA[(size_t)NN * 256];   // aggregation target
__device__ float g_bufB[(size_t)NN * 256];   // post-GEMM features
__device__ float g_x2[BB * 256];             // pooled max
__device__ float g_hidden[BB * 1024];        // fc1 output

// ---------------- small kernels ----------------
__global__ void init_deg_kernel(float* degf, int n) {
    int i = blockIdx.x * blockDim.x + threadIdx.x;
    if (i < n) degf[i] = 1.0f;   // self-loop
}

__global__ void deg_scatter_kernel(const int* __restrict__ col, float* degf, int e) {
    int i = blockIdx.x * blockDim.x + threadIdx.x;
    if (i < e) atomicAdd(&degf[col[i]], 1.0f);
}

__global__ void dinv_kernel(const float* __restrict__ degf, float* dinv, int n) {
    int i = blockIdx.x * blockDim.x + threadIdx.x;
    if (i < n) dinv[i] = rsqrtf(degf[i]);
}

// agg[i] = dinv[i]^2 * h[i]  (self-loop term, also serves as the zero-init)
__global__ void selfloop_init_kernel(const float* __restrict__ h,
                                     const float* __restrict__ dinv,
                                     float* __restrict__ agg, int n, int F) {
    int fc = F >> 2;
    size_t idx = (size_t)blockIdx.x * blockDim.x + threadIdx.x;
    size_t total = (size_t)n * fc;
    if (idx >= total) return;
    int row = (int)(idx / fc);
    int c4  = (int)(idx % fc) << 2;
    float d = dinv[row];
    float s = d * d;
    float4 v = *(const float4*)&h[(size_t)row * F + c4];
    float4 o;
    o.x = s * v.x; o.y = s * v.y; o.z = s * v.z; o.w = s * v.w;
    *(float4*)&agg[(size_t)row * F + c4] = o;
}

// agg[col[e]] += dinv[row]*dinv[col] * h[row[e]]
__global__ void edge_scatter_kernel(const int* __restrict__ erow,
                                    const int* __restrict__ ecol,
                                    const float* __restrict__ dinv,
                                    const float* __restrict__ h,
                                    float* __restrict__ agg, int e, int F) {
    int fc = F >> 2;
    size_t idx = (size_t)blockIdx.x * blockDim.x + threadIdx.x;
    size_t total = (size_t)e * fc;
    if (idx >= total) return;
    int ed = (int)(idx / fc);
    int c4 = (int)(idx % fc) << 2;
    int r = __ldg(&erow[ed]);
    int c = __ldg(&ecol[ed]);
    float nrm = __ldg(&dinv[r]) * __ldg(&dinv[c]);
    float4 v = *(const float4*)&h[(size_t)r * F + c4];
    float* dst = &agg[(size_t)c * F + c4];
    atomicAdd(dst + 0, nrm * v.x);
    atomicAdd(dst + 1, nrm * v.y);
    atomicAdd(dst + 2, nrm * v.z);
    atomicAdd(dst + 3, nrm * v.w);
}

// ---------------- tiled SGEMM: C[Nr,K] = A[Nr,M] @ W[M,K] + bias (opt relu) ----
// BM=128 BN=64 BK=16, 256 threads, 8x4 per-thread tile.
// Requires M % 16 == 0, K % 64 == 0 (true for all call sites).
__global__ __launch_bounds__(256) void sgemm_bias_kernel(
    const float* __restrict__ A, const float* __restrict__ W,
    const float* __restrict__ bias, float* __restrict__ C,
    int Nr, int M, int K, int relu) {
    const int BM = 128, BN = 64, BK = 16, TM = 8, TN = 4;
    __shared__ float As[BK][BM + 4];
    __shared__ float Bs[BK][BN];
    int row0 = blockIdx.y * BM;
    int col0 = blockIdx.x * BN;
    int tid = threadIdx.x;
    int tr = (tid / 16) * TM;
    int tc = (tid % 16) * TN;
    float acc[TM][TN] = {};

    for (int k0 = 0; k0 < M; k0 += BK) {
        // load A tile (transposed into shared), 512 float4 slots, 2 per thread
        #pragma unroll
        for (int l = tid; l < (BM * BK) / 4; l += 256) {
            int r = l >> 2;             // 0..127
            int m4 = (l & 3) << 2;      // 0,4,8,12
            float4 v = make_float4(0.f, 0.f, 0.f, 0.f);
            int gr = row0 + r;
            if (gr < Nr) v = *(const float4*)&A[(size_t)gr * M + k0 + m4];
            As[m4 + 0][r] = v.x;
            As[m4 + 1][r] = v.y;
            As[m4 + 2][r] = v.z;
            As[m4 + 3][r] = v.w;
        }
        // load W tile, 256 float4 slots, 1 per thread
        {
            int m = tid >> 4;             // 0..15
            int c4 = (tid & 15) << 2;     // 0..60
            float4 v = *(const float4*)&W[(size_t)(k0 + m) * K + col0 + c4];
            *(float4*)&Bs[m][c4] = v;
        }
        __syncthreads();
        #pragma unroll
        for (int kk = 0; kk < BK; kk++) {
            float a[TM], b[TN];
            #pragma unroll
            for (int i = 0; i < TM; i++) a[i] = As[kk][tr + i];
            #pragma unroll
            for (int j = 0; j < TN; j++) b[j] = Bs[kk][tc + j];
            #pragma unroll
            for (int i = 0; i < TM; i++)
                #pragma unroll
                for (int j = 0; j < TN; j++)
                    acc[i][j] = fmaf(a[i], b[j], acc[i][j]);
        }
        __syncthreads();
    }

    #pragma unroll
    for (int i = 0; i < TM; i++) {
        int gr = row0 + tr + i;
        if (gr >= Nr) continue;
        #pragma unroll
        for (int j = 0; j < TN; j++) {
            int gc = col0 + tc + j;
            float v = acc[i][j] + bias[gc];
            if (relu) v = fmaxf(v, 0.0f);
            C[(size_t)gr * K + gc] = v;
        }
    }
}

// amvo = mu + eps * exp(0.5*logvar)
__global__ void amvo_kernel(const float* __restrict__ mu,
                            const float* __restrict__ lv,
                            const float* __restrict__ eps,
                            float* __restrict__ amvo, size_t n) {
    size_t i = (size_t)blockIdx.x * blockDim.x + threadIdx.x;
    if (i < n) amvo[i] = fmaf(eps[i], __expf(0.5f * lv[i]), mu[i]);
}

__global__ void zero_kernel(float* p, int n) {
    int i = blockIdx.x * blockDim.x + threadIdx.x;
    if (i < n) p[i] = 0.0f;
}

// x2[batch[i]] = max over nodes (h >= 0 after relu, so int-reinterpret max is valid)
__global__ void segmax_kernel(const float* __restrict__ h,
                              const int* __restrict__ batch,
                              float* __restrict__ x2, int n, int F) {
    size_t idx = (size_t)blockIdx.x * blockDim.x + threadIdx.x;
    size_t total = (size_t)n * F;
    if (idx >= total) return;
    int row = (int)(idx / F);
    int c = (int)(idx % F);
    int b = __ldg(&batch[row]);
    float v = h[idx];
    atomicMax((int*)&x2[(size_t)b * F + c], __float_as_int(v));
}

// ---------------- launch orchestration ----------------
static inline void run_gemm(const float* A, const float* W, const float* bias,
                            float* C, int Nr, int M, int K, int relu) {
    dim3 grid(K / 64, (Nr + 127) / 128);
    sgemm_bias_kernel<<<grid, 256>>>(A, W, bias, C, Nr, M, K, relu);
}

static inline void run_aggregate(const float* h, const int* erow, const int* ecol,
                                 const float* dinv, float* agg, int F) {
    size_t sl = (size_t)NN * (F / 4);
    selfloop_init_kernel<<<(int)((sl + 255) / 256), 256>>>(h, dinv, agg, NN, F);
    size_t es = (size_t)EE * (F / 4);
    edge_scatter_kernel<<<(int)((es + 255) / 256), 256>>>(erow, ecol, dinv, h, agg, EE, F);
}

extern "C" void kernel_launch(void* const* d_in, const int* in_sizes, int n_in,
                              void* d_out, int out_size) {
    const float* x     = (const float*)d_in[0];
    const int*   ei    = (const int*)d_in[1];
    const int*   batch = (const int*)d_in[2];
    const float* eps   = (const float*)d_in[3];
    const float* W1 = (const float*)d_in[4];  const float* b1 = (const float*)d_in[5];
    const float* W2 = (const float*)d_in[6];  const float* b2 = (const float*)d_in[7];
    const float* W3 = (const float*)d_in[8];  const float* b3 = (const float*)d_in[9];
    const float* Wmu = (const float*)d_in[10]; const float* bmu = (const float*)d_in[11];
    const float* Wlv = (const float*)d_in[12]; const float* blv = (const float*)d_in[13];
    const float* fc1w = (const float*)d_in[14]; const float* fc1b = (const float*)d_in[15];
    const float* fc2w = (const float*)d_in[16]; const float* fc2b = (const float*)d_in[17];

    float* out = (float*)d_out;
    float* out_amvo = out;
    float* out_mu   = out + (size_t)NN * 256;
    float* out_lv   = out + 2 * (size_t)NN * 256;
    float* out_pmvo = out + 3 * (size_t)NN * 256;

    float *degf, *dinv, *bufA, *bufB, *x2, *hidden;
    cudaGetSymbolAddress((void**)&degf, g_degf);
    cudaGetSymbolAddress((void**)&dinv, g_dinv);
    cudaGetSymbolAddress((void**)&bufA, g_bufA);
    cudaGetSymbolAddress((void**)&bufB, g_bufB);
    cudaGetSymbolAddress((void**)&x2, g_x2);
    cudaGetSymbolAddress((void**)&hidden, g_hidden);

    const int* erow = ei;
    const int* ecol = ei + EE;

    // degree + normalization
    init_deg_kernel<<<(NN + 255) / 256, 256>>>(degf, NN);
    deg_scatter_kernel<<<(EE + 255) / 256, 256>>>(ecol, degf, EE);
    dinv_kernel<<<(NN + 255) / 256, 256>>>(degf, dinv, NN);

    // layer 1: aggregate(x,64) -> gemm 64->128 +relu
    run_aggregate(x, erow, ecol, dinv, bufA, 64);
    run_gemm(bufA, W1, b1, bufB, NN, 64, 128, 1);

    // layer 2: aggregate(h1,128) -> gemm 128->192 +relu
    run_aggregate(bufB, erow, ecol, dinv, bufA, 128);
    run_gemm(bufA, W2, b2, bufB, NN, 128, 192, 1);

    // layer 3: aggregate(h2,192) -> gemm 192->256 +relu  (bufB = h3)
    run_aggregate(bufB, erow, ecol, dinv, bufA, 192);
    run_gemm(bufA, W3, b3, bufB, NN, 192, 256, 1);

    // shared aggregation for mu / logvar heads
    run_aggregate(bufB, erow, ecol, dinv, bufA, 256);
    run_gemm(bufA, Wmu, bmu, out_mu, NN, 256, 256, 0);
    run_gemm(bufA, Wlv, blv, out_lv, NN, 256, 256, 0);

    // reparameterization
    {
        size_t n = (size_t)NN * 256;
        amvo_kernel<<<(int)((n + 255) / 256), 256>>>(out_mu, out_lv, eps, out_amvo, n);
    }

    // global max pool on h3 + MLP head
    zero_kernel<<<(BB * 256 + 255) / 256, 256>>>(x2, BB * 256);
    {
        size_t n = (size_t)NN * 256;
        segmax_kernel<<<(int)((n + 255) / 256), 256>>>(bufB, batch, x2, NN, 256);
    }
    run_gemm(x2, fc1w, fc1b, hidden, BB, 256, 1024, 1);
    run_gemm(hidden, fc2w, fc2b, out_pmvo, BB, 1024, 128, 0);
}